// round 11
// baseline (speedup 1.0000x reference)
#include <cuda_runtime.h>
#include <cuda_bf16.h>
#include <cstddef>

// WeaveLayer: pure permutation
//   out[b, yb*8 + hi*4 + px, xb*8 + wi*4 + py] = in[b, yb*4+py, xb*4+px, hi*2+wi]
// Shapes: in (B, 768, 768, 4) f32, out (B, 1536, 1536, 1) f32, n=4 fixed.
//
// Strategy: HBM-bound permutation -> stage through shared memory so both the
// global load (float4 per pixel, contiguous along x) and the global store
// (float4 along output row) are perfectly 128B-coalesced.
//
// CTA tile: one yb (4 input rows == 8 output rows) x 32 xb blocks
//   (128 input pixels == 256 output columns).

#define IN_W   768
#define OUT_W  1536
#define SROW   260   // 256 cols + 4 pad (float4-aligned row stride)

__global__ __launch_bounds__(256, 8)
void weave_kernel(const float4* __restrict__ in, float* __restrict__ out)
{
    __shared__ float sm[8 * SROW];

    const int tid = threadIdx.x;
    const int b   = blockIdx.z;
    const int yb  = blockIdx.y;          // 0..191
    const int x0  = blockIdx.x * 128;    // input pixel base (0..640 step 128)

    // ---- Load + scatter: 4 rows x 128 pixels, each pixel is a float4 (4 ch) ----
    const float4* inb = in + ((size_t)b * IN_W + (size_t)yb * 4) * IN_W + x0;

#pragma unroll
    for (int it = 0; it < 2; it++) {
        int i   = tid + it * 256;        // 0..511
        int py  = i >> 7;                // input row within patch, 0..3
        int lx  = i & 127;               // local pixel 0..127
        float4 v = inb[py * IN_W + lx];

        int px  = lx & 3;                // pixel-in-patch (x)
        int xbl = lx >> 2;               // local xb block 0..31
        int c0  = xbl * 8 + py;          // wi=0 column
        // q = hi*2 + wi ; srow = hi*4 + px ; scol = xbl*8 + wi*4 + py
        sm[ px      * SROW + c0    ] = v.x;  // q=0 (hi=0, wi=0)
        sm[ px      * SROW + c0 + 4] = v.y;  // q=1 (hi=0, wi=1)
        sm[(px + 4) * SROW + c0    ] = v.z;  // q=2 (hi=1, wi=0)
        sm[(px + 4) * SROW + c0 + 4] = v.w;  // q=3 (hi=1, wi=1)
    }

    __syncthreads();

    // ---- Store: 8 output rows x 256 cols, fully coalesced float4 stores ----
    float4* outb = reinterpret_cast<float4*>(
        out + ((size_t)b * OUT_W + (size_t)yb * 8) * OUT_W + blockIdx.x * 256);

#pragma unroll
    for (int it = 0; it < 2; it++) {
        int i    = tid + it * 256;       // 0..511
        int orow = i >> 6;               // 0..7
        int c4   = i & 63;               // float4 column index 0..63
        float4 v = *reinterpret_cast<const float4*>(&sm[orow * SROW + c4 * 4]);
        outb[orow * (OUT_W / 4) + c4] = v;
    }
}

extern "C" void kernel_launch(void* const* d_in, const int* in_sizes, int n_in,
                              void* d_out, int out_size)
{
    const float4* in  = reinterpret_cast<const float4*>(d_in[0]);
    float*        out = reinterpret_cast<float*>(d_out);

    // Batch derived from input element count (768*768*4 elems per image)
    int B = in_sizes[0] / (IN_W * IN_W * 4);

    dim3 grid(IN_W / 128,   // 6  : x tiles (128 input pixels each)
              IN_W / 4,     // 192: yb rows
              B);           // 32
    weave_kernel<<<grid, 256>>>(in, out);
}

// round 12
// speedup vs baseline: 1.0032x; 1.0032x over previous
#include <cuda_runtime.h>
#include <cuda_bf16.h>
#include <cstddef>

// WeaveLayer: pure permutation
//   out[b, yb*8 + hi*4 + px, xb*8 + wi*4 + py] = in[b, yb*4+py, xb*4+px, hi*2+wi]
// Shapes: in (B, 768, 768, 4) f32, out (B, 1536, 1536, 1) f32, n=4 fixed.
//
// Strategy: HBM-bound permutation -> stage through shared memory so both the
// global load (float4 per pixel, contiguous along x) and the global store
// (float4 along output row) are perfectly 128B-coalesced.
//
// CTA tile: one yb (4 input rows == 8 output rows) x 32 xb blocks
//   (128 input pixels == 256 output columns).

#define IN_W   768
#define OUT_W  1536
#define SROW   260   // 256 cols + 4 pad (float4-aligned row stride)

__global__ __launch_bounds__(256, 8)
void weave_kernel(const float4* __restrict__ in, float* __restrict__ out)
{
    __shared__ float sm[8 * SROW];

    const int tid = threadIdx.x;
    const int b   = blockIdx.z;
    const int yb  = blockIdx.y;          // 0..191
    const int x0  = blockIdx.x * 128;    // input pixel base (0..640 step 128)

    // ---- Load + scatter: 4 rows x 128 pixels, each pixel is a float4 (4 ch) ----
    const float4* inb = in + ((size_t)b * IN_W + (size_t)yb * 4) * IN_W + x0;

#pragma unroll
    for (int it = 0; it < 2; it++) {
        int i   = tid + it * 256;        // 0..511
        int py  = i >> 7;                // input row within patch, 0..3
        int lx  = i & 127;               // local pixel 0..127
        float4 v = inb[py * IN_W + lx];

        int px  = lx & 3;                // pixel-in-patch (x)
        int xbl = lx >> 2;               // local xb block 0..31
        int c0  = xbl * 8 + py;          // wi=0 column
        // q = hi*2 + wi ; srow = hi*4 + px ; scol = xbl*8 + wi*4 + py
        sm[ px      * SROW + c0    ] = v.x;  // q=0 (hi=0, wi=0)
        sm[ px      * SROW + c0 + 4] = v.y;  // q=1 (hi=0, wi=1)
        sm[(px + 4) * SROW + c0    ] = v.z;  // q=2 (hi=1, wi=0)
        sm[(px + 4) * SROW + c0 + 4] = v.w;  // q=3 (hi=1, wi=1)
    }

    __syncthreads();

    // ---- Store: 8 output rows x 256 cols, fully coalesced float4 stores ----
    float4* outb = reinterpret_cast<float4*>(
        out + ((size_t)b * OUT_W + (size_t)yb * 8) * OUT_W + blockIdx.x * 256);

#pragma unroll
    for (int it = 0; it < 2; it++) {
        int i    = tid + it * 256;       // 0..511
        int orow = i >> 6;               // 0..7
        int c4   = i & 63;               // float4 column index 0..63
        float4 v = *reinterpret_cast<const float4*>(&sm[orow * SROW + c4 * 4]);
        outb[orow * (OUT_W / 4) + c4] = v;
    }
}

extern "C" void kernel_launch(void* const* d_in, const int* in_sizes, int n_in,
                              void* d_out, int out_size)
{
    const float4* in  = reinterpret_cast<const float4*>(d_in[0]);
    float*        out = reinterpret_cast<float*>(d_out);

    // Batch derived from input element count (768*768*4 elems per image)
    int B = in_sizes[0] / (IN_W * IN_W * 4);

    dim3 grid(IN_W / 128,   // 6  : x tiles (128 input pixels each)
              IN_W / 4,     // 192: yb rows
              B);           // 32
    weave_kernel<<<grid, 256>>>(in, out);
}

// round 13
// speedup vs baseline: 1.0035x; 1.0004x over previous
#include <cuda_runtime.h>
#include <cuda_bf16.h>
#include <cstddef>

// WeaveLayer: pure permutation
//   out[b, yb*8 + hi*4 + px, xb*8 + wi*4 + py] = in[b, yb*4+py, xb*4+px, hi*2+wi]
// Shapes: in (B, 768, 768, 4) f32, out (B, 1536, 1536, 1) f32, n=4 fixed.
//
// R12: 90.2us, DRAM 79.9%, HBM 6331 GB/s — at the LTS/HBM mixed-stream limit.
// R13 change: streaming cache hints (__ldcs/__stcs) so the read-once /
// write-once streams don't thrash L2 allocation, + explicit back-to-back
// load batching for guaranteed MLP=2 on the global loads.
//
// CTA tile: one yb (4 input rows == 8 output rows) x 32 xb blocks
//   (128 input pixels == 256 output columns).

#define IN_W   768
#define OUT_W  1536
#define SROW   260   // 256 cols + 4 pad (float4-aligned row stride)

__global__ __launch_bounds__(256, 8)
void weave_kernel(const float4* __restrict__ in, float* __restrict__ out)
{
    __shared__ float sm[8 * SROW];

    const int tid = threadIdx.x;
    const int b   = blockIdx.z;
    const int yb  = blockIdx.y;          // 0..191
    const int x0  = blockIdx.x * 128;    // input pixel base

    // ---- Load: 4 rows x 128 pixels, each pixel one float4 (4 channels) ----
    const float4* inb = in + ((size_t)b * IN_W + (size_t)yb * 4) * IN_W + x0;

    // Both global loads issued back-to-back (MLP=2) with streaming hint:
    // data is read exactly once, don't let it occupy L2.
    const int i0  = tid;            // 0..255
    const int i1  = tid + 256;      // 256..511
    const int py0 = i0 >> 7, lx0 = i0 & 127;
    const int py1 = i1 >> 7, lx1 = i1 & 127;

    float4 v0 = __ldcs(&inb[py0 * IN_W + lx0]);
    float4 v1 = __ldcs(&inb[py1 * IN_W + lx1]);

    // ---- Scatter into output-ordered smem ----
    {
        int px  = lx0 & 3;
        int c0  = (lx0 >> 2) * 8 + py0;  // xbl*8 + py (wi=0 column)
        sm[ px      * SROW + c0    ] = v0.x;  // q=0 (hi=0, wi=0)
        sm[ px      * SROW + c0 + 4] = v0.y;  // q=1 (hi=0, wi=1)
        sm[(px + 4) * SROW + c0    ] = v0.z;  // q=2 (hi=1, wi=0)
        sm[(px + 4) * SROW + c0 + 4] = v0.w;  // q=3 (hi=1, wi=1)
    }
    {
        int px  = lx1 & 3;
        int c0  = (lx1 >> 2) * 8 + py1;
        sm[ px      * SROW + c0    ] = v1.x;
        sm[ px      * SROW + c0 + 4] = v1.y;
        sm[(px + 4) * SROW + c0    ] = v1.z;
        sm[(px + 4) * SROW + c0 + 4] = v1.w;
    }

    __syncthreads();

    // ---- Store: 8 output rows x 256 cols, coalesced float4 streaming stores ----
    float4* outb = reinterpret_cast<float4*>(
        out + ((size_t)b * OUT_W + (size_t)yb * 8) * OUT_W + blockIdx.x * 256);

#pragma unroll
    for (int it = 0; it < 2; it++) {
        int i    = tid + it * 256;       // 0..511
        int orow = i >> 6;               // 0..7
        int c4   = i & 63;               // float4 column index 0..63
        float4 v = *reinterpret_cast<const float4*>(&sm[orow * SROW + c4 * 4]);
        __stcs(&outb[orow * (OUT_W / 4) + c4], v);
    }
}

extern "C" void kernel_launch(void* const* d_in, const int* in_sizes, int n_in,
                              void* d_out, int out_size)
{
    const float4* in  = reinterpret_cast<const float4*>(d_in[0]);
    float*        out = reinterpret_cast<float*>(d_out);

    int B = in_sizes[0] / (IN_W * IN_W * 4);

    dim3 grid(IN_W / 128,   // 6  : x tiles (128 input pixels each)
              IN_W / 4,     // 192: yb rows
              B);           // 32
    weave_kernel<<<grid, 256>>>(in, out);
}